// round 2
// baseline (speedup 1.0000x reference)
#include <cuda_runtime.h>
#include <cstdint>

#define N_ROWS 32768
#define D      256
#define K      8192
#define BM     128
#define BN     128
#define DK     64
#define NT     256
#define DECAYF 0.8f
#define OMDF   0.2f
#define EPSF   1e-5f

// Output layout (concatenated f32, reference return order)
#define O_Q    0
#define O_IND  8388608
#define O_CS   8421376
#define O_EA   8429568
#define O_EMB  10526720
#define O_TOT  12623872

// Scratch (device globals — no runtime allocation allowed)
__device__ float g_enorm[K];
__device__ int   g_ind[N_ROWS];
__device__ float g_counts[K];
__device__ float g_esum[K * D];
__device__ float g_S;

// smem partition for argmax kernel
#define XS_STRIDE 260                         // 128 rows x 256 d, padded (260 mod 32 = 4 -> no x bank conflicts)
#define ES_STRIDE 130                         // 128 codes + pad (even -> 8B-aligned pair reads)
#define XS_FLOATS (BM * XS_STRIDE)            // 33280
#define ES_FLOATS (2 * DK * ES_STRIDE)        // 16640
#define SM_FLOATS (XS_FLOATS + ES_FLOATS + BM + BM)
#define SM_BYTES  (SM_FLOATS * 4)

__device__ __forceinline__ void ffma2(unsigned long long& acc, unsigned long long a, unsigned long long b) {
    asm("fma.rn.f32x2 %0, %1, %2, %0;" : "+l"(acc) : "l"(a), "l"(b));
}
__device__ __forceinline__ unsigned long long dup2(float v) {
    unsigned long long r;
    asm("mov.b64 %0, {%1, %1};" : "=l"(r) : "f"(v));
    return r;
}
__device__ __forceinline__ float2 unpk(unsigned long long v) {
    float2 r;
    asm("mov.b64 {%0, %1}, %2;" : "=f"(r.x), "=f"(r.y) : "l"(v));
    return r;
}

// ---------------- zero scratch ----------------
__global__ void zero_kernel() {
    int i = blockIdx.x * blockDim.x + threadIdx.x;
    if (i < K * D) g_esum[i] = 0.0f;
    if (i < K)     g_counts[i] = 0.0f;
    if (i == 0)    g_S = 0.0f;
}

// ---------------- ||e_k||^2 ----------------
__global__ void enorm_kernel(const float* __restrict__ embed) {
    int w = (blockIdx.x * blockDim.x + threadIdx.x) >> 5;
    int lane = threadIdx.x & 31;
    if (w >= K) return;
    const float4* p = reinterpret_cast<const float4*>(embed + (size_t)w * D);
    float s = 0.0f;
#pragma unroll
    for (int h = 0; h < 2; h++) {
        float4 v = p[h * 32 + lane];
        s += v.x * v.x + v.y * v.y + v.z * v.z + v.w * v.w;
    }
#pragma unroll
    for (int off = 16; off >= 1; off >>= 1) s += __shfl_xor_sync(0xffffffffu, s, off);
    if (lane == 0) g_enorm[w] = s;
}

// ---------------- argmax_k (2 x.e_k - ||e_k||^2), fp32 exact, FFMA2 packed over code pairs ----------------
__global__ void __launch_bounds__(NT, 1)
argmax_kernel(const float* __restrict__ x, const float* __restrict__ embed) {
    extern __shared__ float sm[];
    float* xs      = sm;
    float* es      = sm + XS_FLOATS;
    float* rowBest = es + ES_FLOATS;
    int*   rowIdx  = reinterpret_cast<int*>(rowBest + BM);

    const int tid = threadIdx.x;
    const int tx = tid & 15, ty = tid >> 4;
    const int r0 = blockIdx.x * BM;

    // Load the 128x256 x tile once (32 float4 per thread)
#pragma unroll
    for (int it = 0; it < 32; it++) {
        int l = it * NT + tid;               // 0..8191 float4s
        int row = l >> 6, f4 = l & 63;
        float4 v = *reinterpret_cast<const float4*>(x + (size_t)(r0 + row) * D + f4 * 4);
        *reinterpret_cast<float4*>(xs + row * XS_STRIDE + f4 * 4) = v;
    }
    if (tid < BM) { rowBest[tid] = __int_as_float(0xff800000); rowIdx[tid] = 0x7fffffff; }

    // stage chunk 0 of embed into registers (8 float4/thread)
    float4 u[8];
#pragma unroll
    for (int it = 0; it < 8; it++) {
        int l = it * NT + tid;               // 0..2047: 128 codes x 16 f4
        int cl = l >> 4, f4 = l & 15;
        u[it] = *reinterpret_cast<const float4*>(embed + (size_t)cl * D + f4 * 4);
    }
    __syncthreads();

    unsigned long long acc[32];
#pragma unroll
    for (int q = 0; q < 32; q++) acc[q] = 0ull;

    for (int c = 0; c < 256; c++) {          // 64 code chunks x 4 d-chunks
        float* eb = es + (c & 1) * (DK * ES_STRIDE);
        // transpose-store staged chunk: es[kd][code]
#pragma unroll
        for (int it = 0; it < 8; it++) {
            int l = it * NT + tid;
            int cl = l >> 4, f4 = l & 15;
            float4 v = u[it];
            eb[(f4 * 4 + 0) * ES_STRIDE + cl] = v.x;
            eb[(f4 * 4 + 1) * ES_STRIDE + cl] = v.y;
            eb[(f4 * 4 + 2) * ES_STRIDE + cl] = v.z;
            eb[(f4 * 4 + 3) * ES_STRIDE + cl] = v.w;
        }
        __syncthreads();

        if (c < 255) {                       // prefetch next chunk under compute
            int cn = c + 1;
            int n0 = (cn >> 2) * BN, doff = (cn & 3) * DK;
#pragma unroll
            for (int it = 0; it < 8; it++) {
                int l = it * NT + tid;
                int cl = l >> 4, f4 = l & 15;
                u[it] = *reinterpret_cast<const float4*>(embed + (size_t)(n0 + cl) * D + doff + f4 * 4);
            }
        }

        const int doff = (c & 3) * DK;
        const float* xr0 = xs + ty * XS_STRIDE + doff;
#pragma unroll 8
        for (int kd = 0; kd < DK; kd++) {
            const float* er = eb + kd * ES_STRIDE;
            unsigned long long ev[4];
#pragma unroll
            for (int p = 0; p < 4; p++)
                ev[p] = *reinterpret_cast<const unsigned long long*>(er + (p * 16 + tx) * 2);
#pragma unroll
            for (int i = 0; i < 8; i++) {
                unsigned long long xd = dup2(xr0[i * 16 * XS_STRIDE + kd]);
#pragma unroll
                for (int p = 0; p < 4; p++) ffma2(acc[i * 4 + p], xd, ev[p]);
            }
        }

        if ((c & 3) == 3) {                  // end of a 128-code group: argmax update
            int n0 = (c >> 2) * BN;
            float en0[4], en1[4];
#pragma unroll
            for (int p = 0; p < 4; p++) {
                int cp = p * 16 + tx;
                en0[p] = g_enorm[n0 + cp * 2];
                en1[p] = g_enorm[n0 + cp * 2 + 1];
            }
#pragma unroll
            for (int i = 0; i < 8; i++) {
                float best = __int_as_float(0xff800000);
                int bi = 0x7fffffff;
#pragma unroll
                for (int p = 0; p < 4; p++) {
                    float2 f = unpk(acc[i * 4 + p]);
                    acc[i * 4 + p] = 0ull;
                    int c0 = n0 + (p * 16 + tx) * 2;
                    float s0 = 2.0f * f.x - en0[p];
                    float s1 = 2.0f * f.y - en1[p];
                    if (s0 > best || (s0 == best && c0 < bi))     { best = s0; bi = c0; }
                    if (s1 > best || (s1 == best && c0 + 1 < bi)) { best = s1; bi = c0 + 1; }
                }
#pragma unroll
                for (int off = 8; off >= 1; off >>= 1) {
                    float s2 = __shfl_xor_sync(0xffffffffu, best, off);
                    int   i2 = __shfl_xor_sync(0xffffffffu, bi, off);
                    if (s2 > best || (s2 == best && i2 < bi)) { best = s2; bi = i2; }
                }
                if (tx == 0) {
                    int r = i * 16 + ty;
                    if (best > rowBest[r] || (best == rowBest[r] && bi < rowIdx[r])) {
                        rowBest[r] = best; rowIdx[r] = bi;
                    }
                }
            }
        }
    }
    __syncthreads();
    if (tid < BM) g_ind[r0 + tid] = rowIdx[tid];
}

// ---------------- gather quantize + scatter counts/embed_sum + indices ----------------
__global__ void scatter_kernel(const float* __restrict__ x, const float* __restrict__ embed,
                               float* __restrict__ out, int out_size) {
    int w = (blockIdx.x * blockDim.x + threadIdx.x) >> 5;
    int lane = threadIdx.x & 31;
    if (w >= N_ROWS) return;
    int idx = g_ind[w];
    const float4* esrc = reinterpret_cast<const float4*>(embed + (size_t)idx * D);
    const float4* xsrc = reinterpret_cast<const float4*>(x + (size_t)w * D);
    float4* qdst = reinterpret_cast<float4*>(out + (size_t)w * D);
    bool wq = (out_size >= O_IND);
#pragma unroll
    for (int h = 0; h < 2; h++) {
        int j = h * 32 + lane;
        if (wq) qdst[j] = esrc[j];
        float4 xv = xsrc[j];
        float* dst = g_esum + (size_t)idx * D + j * 4;
        atomicAdd(dst + 0, xv.x);
        atomicAdd(dst + 1, xv.y);
        atomicAdd(dst + 2, xv.z);
        atomicAdd(dst + 3, xv.w);
    }
    if (lane == 0) {
        atomicAdd(&g_counts[idx], 1.0f);
        if (out_size >= O_CS) out[O_IND + w] = (float)idx;
    }
}

// ---------------- new_cluster_size + sum reduction ----------------
__global__ void cs_kernel(const float* __restrict__ cs, float* __restrict__ out, int out_size) {
    __shared__ float red[8];
    int k = blockIdx.x * blockDim.x + threadIdx.x;
    float v = 0.0f;
    if (k < K) {
        v = cs[k] * DECAYF + g_counts[k] * OMDF;
        if (out_size >= O_EA) out[O_CS + k] = v;
    }
#pragma unroll
    for (int off = 16; off >= 1; off >>= 1) v += __shfl_xor_sync(0xffffffffu, v, off);
    int lane = threadIdx.x & 31, wid = threadIdx.x >> 5;
    if (lane == 0) red[wid] = v;
    __syncthreads();
    if (wid == 0) {
        float s = (lane < (blockDim.x >> 5)) ? red[lane] : 0.0f;
#pragma unroll
        for (int off = 4; off >= 1; off >>= 1) s += __shfl_xor_sync(0xffffffffu, s, off);
        if (lane == 0) atomicAdd(&g_S, s);
    }
}

// ---------------- new_embed_avg + new_embed ----------------
__global__ void finalize_kernel(const float* __restrict__ cs, const float* __restrict__ ea,
                                float* __restrict__ out, int out_size) {
    int i = blockIdx.x * blockDim.x + threadIdx.x;
    if (i >= K * D) return;
    int k = i >> 8;
    float nea = ea[i] * DECAYF + g_esum[i] * OMDF;
    float ncs = cs[k] * DECAYF + g_counts[k] * OMDF;
    float S = g_S;
    float smoothed = (ncs + EPSF) / (S + (float)K * EPSF) * S;
    if (out_size >= O_EMB) out[O_EA + i] = nea;
    if (out_size >= O_TOT) out[O_EMB + i] = nea / smoothed;
}

extern "C" void kernel_launch(void* const* d_in, const int* in_sizes, int n_in,
                              void* d_out, int out_size) {
    const float* x     = (const float*)d_in[0];
    const float* embed = (const float*)d_in[1];
    const float* cs    = (const float*)d_in[2];
    const float* ea    = (const float*)d_in[3];
    float* out = (float*)d_out;

    cudaFuncSetAttribute(argmax_kernel, cudaFuncAttributeMaxDynamicSharedMemorySize, SM_BYTES);

    zero_kernel<<<(K * D + 1023) / 1024, 1024>>>();
    enorm_kernel<<<K / 8, 256>>>(embed);
    argmax_kernel<<<N_ROWS / BM, NT, SM_BYTES>>>(x, embed);
    scatter_kernel<<<N_ROWS / 8, 256>>>(x, embed, out, out_size);
    cs_kernel<<<(K + 255) / 256, 256>>>(cs, out, out_size);
    finalize_kernel<<<(K * D + 255) / 256, 256>>>(cs, ea, out, out_size);
}

// round 10
// speedup vs baseline: 2.2377x; 2.2377x over previous
#include <cuda_runtime.h>
#include <cstdint>

#define N_ROWS 32768
#define D      256
#define K      8192
#define BM     128
#define NT     256
#define DECAYF 0.8f
#define OMDF   0.2f
#define EPSF   1e-5f
#define TH     0.25f

// Output layout (concatenated f32, reference return order)
#define O_Q    0
#define O_IND  8388608
#define O_CS   8421376
#define O_EA   8429568
#define O_EMB  10526720
#define O_TOT  12623872

// smem (float2 units)
#define SA     260            // float2 stride per x row-pair
#define SB     132            // float2 stride per e k-quad
#define XS_F2  (64 * SA)      // 16640 float2 = 133120 B
#define BS_F2  (16 * SB)      // 2112 float2 = 16896 B per buffer
#define SM_BYTES ((XS_F2 + 2 * BS_F2) * 8)   // 166912

// bank-conflict-free swizzled B index: kq in [0,16), code in [0,128)
__device__ __forceinline__ int bidx(int kq, int code) {
    return kq * SB + (code ^ ((kq >> 2) << 2) ^ ((kq & 3) << 3));
}

// Scratch
__device__ float g_enorm[K];
__device__ int   g_ind[N_ROWS];
__device__ float g_counts[K];
__device__ float g_esum[K * D];
__device__ float g_S;
__device__ int   g_nflag;
__device__ int   g_flag[N_ROWS];
__device__ int   g_cand[N_ROWS * 3];

__device__ __forceinline__ void mma_tf32(float* c, const uint32_t* a, const uint32_t* b) {
    asm volatile("mma.sync.aligned.m16n8k8.row.col.f32.tf32.tf32.f32 "
        "{%0,%1,%2,%3}, {%4,%5,%6,%7}, {%8,%9}, {%0,%1,%2,%3};"
        : "+f"(c[0]), "+f"(c[1]), "+f"(c[2]), "+f"(c[3])
        : "r"(a[0]), "r"(a[1]), "r"(a[2]), "r"(a[3]), "r"(b[0]), "r"(b[1]));
}

__device__ __forceinline__ void upd3(float s, int c, float* bs, int* bi) {
    if (s > bs[0])      { bs[2]=bs[1]; bi[2]=bi[1]; bs[1]=bs[0]; bi[1]=bi[0]; bs[0]=s; bi[0]=c; }
    else if (s > bs[1]) { bs[2]=bs[1]; bi[2]=bi[1]; bs[1]=s; bi[1]=c; }
    else if (s > bs[2]) { bs[2]=s; bi[2]=c; }
}

// ---------------- zero scratch ----------------
__global__ void zero_kernel() {
    int i = blockIdx.x * blockDim.x + threadIdx.x;
    if (i < K * D) g_esum[i] = 0.0f;
    if (i < K)     g_counts[i] = 0.0f;
    if (i == 0)  { g_S = 0.0f; g_nflag = 0; }
}

// ---------------- ||e_k||^2 ----------------
__global__ void enorm_kernel(const float* __restrict__ embed) {
    int w = (blockIdx.x * blockDim.x + threadIdx.x) >> 5;
    int lane = threadIdx.x & 31;
    if (w >= K) return;
    const float4* p = reinterpret_cast<const float4*>(embed + (size_t)w * D);
    float s = 0.0f;
#pragma unroll
    for (int h = 0; h < 2; h++) {
        float4 v = p[h * 32 + lane];
        s += v.x * v.x + v.y * v.y + v.z * v.z + v.w * v.w;
    }
#pragma unroll
    for (int off = 16; off >= 1; off >>= 1) s += __shfl_xor_sync(0xffffffffu, s, off);
    if (lane == 0) g_enorm[w] = s;
}

// ---------------- tf32 mma.sync scoring + streaming top-3 argmax ----------------
__global__ void __launch_bounds__(NT, 1)
argmax_mma_kernel(const float* __restrict__ x, const float* __restrict__ embed) {
    extern __shared__ float2 smem2[];
    float2* Xs = smem2;                    // x tile: row-pair interleaved
    float2* Bs = smem2 + XS_F2;            // e chunks: double buffered; reused as merge buffer at end

    const int tid = threadIdx.x;
    const int wid = tid >> 5, lane = tid & 31;
    const int lg = lane >> 2, lm = lane & 3;
    const int wm = wid >> 2, wn = wid & 3;         // warp grid 2m x 4n
    const int r0 = blockIdx.x * BM;

    // ---- stage x tile: pairs (row, row+8) as float2 ----
#pragma unroll
    for (int t = 0; t < 16; t++) {
        int task = tid + t * NT;                   // 4096 tasks: 64 rowpairs x 64 col-quads
        int rp = task >> 6, cq = task & 63;
        int row = ((rp >> 3) << 4) + (rp & 7);
        const float4 lo = *reinterpret_cast<const float4*>(x + (size_t)(r0 + row) * D + cq * 4);
        const float4 hi = *reinterpret_cast<const float4*>(x + (size_t)(r0 + row + 8) * D + cq * 4);
        float2* dst = Xs + rp * SA + cq * 4;
        dst[0] = make_float2(lo.x, hi.x);
        dst[1] = make_float2(lo.y, hi.y);
        dst[2] = make_float2(lo.z, hi.z);
        dst[3] = make_float2(lo.w, hi.w);
    }
    // ---- stage e chunk 0 (tile 0, d 0..31): pairs (k, k+4), swizzled ----
#pragma unroll
    for (int t = 0; t < 2; t++) {
        int task = tid + t * NT;                   // 512 tasks: 128 codes x 4 k-octets
        int code = task >> 2, koct = task & 3;
        const float4* gp = reinterpret_cast<const float4*>(embed + (size_t)code * D + koct * 8);
        float4 lo = gp[0], hi = gp[1];
        const float* lof = reinterpret_cast<const float*>(&lo);
        const float* hif = reinterpret_cast<const float*>(&hi);
#pragma unroll
        for (int km = 0; km < 4; km++)
            Bs[bidx(koct * 4 + km, code)] = make_float2(lof[km], hif[km]);
    }
    __syncthreads();

    float acc[64];
    float bs[24]; int bi[24];
#pragma unroll
    for (int i = 0; i < 24; i++) { bs[i] = __int_as_float(0xff800000); bi[i] = 0x7fffffff; }

    for (int it = 0; it < 512; it++) {             // 64 code tiles x 8 d-chunks
        const int nt = it >> 3, kc = it & 7;
        if (kc == 0) {
#pragma unroll
            for (int i = 0; i < 64; i++) acc[i] = 0.0f;
        }
        // prefetch next e chunk into registers
        float4 pf[4];
        if (it < 511) {
            int itn = it + 1, ntn = itn >> 3, kcn = itn & 7;
#pragma unroll
            for (int t = 0; t < 2; t++) {
                int task = tid + t * NT;
                int code = task >> 2, koct = task & 3;
                const float4* gp = reinterpret_cast<const float4*>(
                    embed + (size_t)(ntn * 128 + code) * D + kcn * 32 + koct * 8);
                pf[2 * t] = gp[0]; pf[2 * t + 1] = gp[1];
            }
        }
        // compute: 4 k8 steps on buffer it&1
        const float2* Bp = Bs + (it & 1) * BS_F2;
#pragma unroll
        for (int kk = 0; kk < 4; kk++) {
            const int c0 = kc * 32 + kk * 8;
            uint32_t a[4][4];
#pragma unroll
            for (int mf = 0; mf < 4; mf++) {
                int rp = (wm * 4 + mf) * 8 + lg;
                float2 v0 = Xs[rp * SA + c0 + lm];
                float2 v1 = Xs[rp * SA + c0 + lm + 4];
                a[mf][0] = __float_as_uint(v0.x); a[mf][1] = __float_as_uint(v0.y);
                a[mf][2] = __float_as_uint(v1.x); a[mf][3] = __float_as_uint(v1.y);
            }
            uint32_t b[4][2];
#pragma unroll
            for (int nf = 0; nf < 4; nf++) {
                float2 w = Bp[bidx(kk * 4 + lm, wn * 32 + nf * 8 + lg)];
                b[nf][0] = __float_as_uint(w.x); b[nf][1] = __float_as_uint(w.y);
            }
#pragma unroll
            for (int mf = 0; mf < 4; mf++)
#pragma unroll
                for (int nf = 0; nf < 4; nf++)
                    mma_tf32(acc + (mf * 4 + nf) * 4, a[mf], b[nf]);
        }
        // epilogue at end of code tile
        if (kc == 7) {
            int ntb = nt * 128 + wn * 32;
#pragma unroll
            for (int nf = 0; nf < 4; nf++) {
                int cb = ntb + nf * 8 + 2 * lm;
                float e0 = __ldg(g_enorm + cb), e1 = __ldg(g_enorm + cb + 1);
#pragma unroll
                for (int mf = 0; mf < 4; mf++) {
                    float* ac = acc + (mf * 4 + nf) * 4;
                    upd3(fmaf(2.0f, ac[0], -e0), cb,     bs + (mf * 2) * 3,     bi + (mf * 2) * 3);
                    upd3(fmaf(2.0f, ac[1], -e1), cb + 1, bs + (mf * 2) * 3,     bi + (mf * 2) * 3);
                    upd3(fmaf(2.0f, ac[2], -e0), cb,     bs + (mf * 2 + 1) * 3, bi + (mf * 2 + 1) * 3);
                    upd3(fmaf(2.0f, ac[3], -e1), cb + 1, bs + (mf * 2 + 1) * 3, bi + (mf * 2 + 1) * 3);
                }
            }
        }
        // store prefetched chunk into the other buffer (swizzled -> conflict-free)
        if (it < 511) {
            float2* bb = Bs + ((it + 1) & 1) * BS_F2;
#pragma unroll
            for (int t = 0; t < 2; t++) {
                int task = tid + t * NT;
                int code = task >> 2, koct = task & 3;
                const float* lof = reinterpret_cast<const float*>(&pf[2 * t]);
                const float* hif = reinterpret_cast<const float*>(&pf[2 * t + 1]);
#pragma unroll
                for (int km = 0; km < 4; km++)
                    bb[bidx(koct * 4 + km, code)] = make_float2(lof[km], hif[km]);
            }
        }
        __syncthreads();
    }

    // ---- merge top-3: (1) across the 4 lm lanes sharing each row, (2) ACROSS THE 4 wn WARPS ----
    float2* mg = Bs;   // reuse dead B buffers: [128 rows][4 wn][3] float2(score, idx)
#pragma unroll
    for (int rid = 0; rid < 8; rid++) {
        float* s = bs + rid * 3; int* ii = bi + rid * 3;
#pragma unroll
        for (int off = 1; off <= 2; off <<= 1) {
            float r0s = __shfl_xor_sync(0xffffffffu, s[0], off);
            float r1s = __shfl_xor_sync(0xffffffffu, s[1], off);
            float r2s = __shfl_xor_sync(0xffffffffu, s[2], off);
            int r0i = __shfl_xor_sync(0xffffffffu, ii[0], off);
            int r1i = __shfl_xor_sync(0xffffffffu, ii[1], off);
            int r2i = __shfl_xor_sync(0xffffffffu, ii[2], off);
            upd3(r0s, r0i, s, ii);
            upd3(r1s, r1i, s, ii);
            upd3(r2s, r2i, s, ii);
        }
        if (lm == 0) {
            int mf = rid >> 1, half = rid & 1;
            int rloc = wm * 64 + mf * 16 + half * 8 + lg;   // 0..127
#pragma unroll
            for (int q = 0; q < 3; q++)
                mg[(rloc * 4 + wn) * 3 + q] = make_float2(s[q], __int_as_float(ii[q]));
        }
    }
    __syncthreads();
    if (tid < BM) {
        float fs[3]; int fi[3];
#pragma unroll
        for (int q = 0; q < 3; q++) { fs[q] = __int_as_float(0xff800000); fi[q] = 0x7fffffff; }
#pragma unroll
        for (int w = 0; w < 4; w++)
#pragma unroll
            for (int q = 0; q < 3; q++) {
                float2 v = mg[(tid * 4 + w) * 3 + q];
                upd3(v.x, __float_as_int(v.y), fs, fi);
            }
        int row = r0 + tid;
        g_ind[row] = fi[0];
        if (fs[0] - fs[1] < TH) {
            int nc = (fs[0] - fs[2] < TH) ? 3 : 2;
            g_cand[row * 3 + 0] = fi[0];
            g_cand[row * 3 + 1] = fi[1];
            g_cand[row * 3 + 2] = fi[2];
            int p = atomicAdd(&g_nflag, 1);
            g_flag[p] = row | (nc << 20);
        }
    }
}

// ---------------- exact fp32 rescore of flagged rows' candidates ----------------
__global__ void cleanup_kernel(const float* __restrict__ x, const float* __restrict__ embed) {
    int gw = (blockIdx.x * blockDim.x + threadIdx.x) >> 5;
    int lane = threadIdx.x & 31;
    int nw = (gridDim.x * blockDim.x) >> 5;
    int nf = g_nflag;
    for (int j = gw; j < nf; j += nw) {
        int e = g_flag[j];
        int row = e & 0xFFFFF, nc = e >> 20;
        const float4* xp = reinterpret_cast<const float4*>(x + (size_t)row * D);
        float4 xa = xp[lane], xb = xp[32 + lane];
        float best = __int_as_float(0xff800000);
        int bidx2 = 0x7fffffff;
        for (int q = 0; q < nc; q++) {
            int cand = g_cand[row * 3 + q];
            const float4* ep = reinterpret_cast<const float4*>(embed + (size_t)cand * D);
            float4 ea = ep[lane], eb = ep[32 + lane];
            float s = xa.x * ea.x + xa.y * ea.y + xa.z * ea.z + xa.w * ea.w
                    + xb.x * eb.x + xb.y * eb.y + xb.z * eb.z + xb.w * eb.w;
#pragma unroll
            for (int off = 16; off >= 1; off >>= 1) s += __shfl_xor_sync(0xffffffffu, s, off);
            s = 2.0f * s - g_enorm[cand];
            if (s > best || (s == best && cand < bidx2)) { best = s; bidx2 = cand; }
        }
        if (lane == 0) g_ind[row] = bidx2;
    }
}

// ---------------- gather quantize + scatter counts/embed_sum + indices ----------------
__global__ void scatter_kernel(const float* __restrict__ x, const float* __restrict__ embed,
                               float* __restrict__ out, int out_size) {
    int w = (blockIdx.x * blockDim.x + threadIdx.x) >> 5;
    int lane = threadIdx.x & 31;
    if (w >= N_ROWS) return;
    int idx = g_ind[w];
    const float4* esrc = reinterpret_cast<const float4*>(embed + (size_t)idx * D);
    const float4* xsrc = reinterpret_cast<const float4*>(x + (size_t)w * D);
    float4* qdst = reinterpret_cast<float4*>(out + (size_t)w * D);
    bool wq = (out_size >= O_IND);
#pragma unroll
    for (int h = 0; h < 2; h++) {
        int j = h * 32 + lane;
        if (wq) qdst[j] = esrc[j];
        float4 xv = xsrc[j];
        float* dst = g_esum + (size_t)idx * D + j * 4;
        atomicAdd(dst + 0, xv.x);
        atomicAdd(dst + 1, xv.y);
        atomicAdd(dst + 2, xv.z);
        atomicAdd(dst + 3, xv.w);
    }
    if (lane == 0) {
        atomicAdd(&g_counts[idx], 1.0f);
        if (out_size >= O_CS) out[O_IND + w] = (float)idx;
    }
}

// ---------------- new_cluster_size + sum reduction ----------------
__global__ void cs_kernel(const float* __restrict__ cs, float* __restrict__ out, int out_size) {
    __shared__ float red[8];
    int k = blockIdx.x * blockDim.x + threadIdx.x;
    float v = 0.0f;
    if (k < K) {
        v = cs[k] * DECAYF + g_counts[k] * OMDF;
        if (out_size >= O_EA) out[O_CS + k] = v;
    }
#pragma unroll
    for (int off = 16; off >= 1; off >>= 1) v += __shfl_xor_sync(0xffffffffu, v, off);
    int lane = threadIdx.x & 31, wid = threadIdx.x >> 5;
    if (lane == 0) red[wid] = v;
    __syncthreads();
    if (wid == 0) {
        float s = (lane < (blockDim.x >> 5)) ? red[lane] : 0.0f;
#pragma unroll
        for (int off = 4; off >= 1; off >>= 1) s += __shfl_xor_sync(0xffffffffu, s, off);
        if (lane == 0) atomicAdd(&g_S, s);
    }
}

// ---------------- new_embed_avg + new_embed ----------------
__global__ void finalize_kernel(const float* __restrict__ cs, const float* __restrict__ ea,
                                float* __restrict__ out, int out_size) {
    int i = blockIdx.x * blockDim.x + threadIdx.x;
    if (i >= K * D) return;
    int k = i >> 8;
    float nea = ea[i] * DECAYF + g_esum[i] * OMDF;
    float ncs = cs[k] * DECAYF + g_counts[k] * OMDF;
    float S = g_S;
    float smoothed = (ncs + EPSF) / (S + (float)K * EPSF) * S;
    if (out_size >= O_EMB) out[O_EA + i] = nea;
    if (out_size >= O_TOT) out[O_EMB + i] = nea / smoothed;
}

extern "C" void kernel_launch(void* const* d_in, const int* in_sizes, int n_in,
                              void* d_out, int out_size) {
    const float* x     = (const float*)d_in[0];
    const float* embed = (const float*)d_in[1];
    const float* cs    = (const float*)d_in[2];
    const float* ea    = (const float*)d_in[3];
    float* out = (float*)d_out;

    cudaFuncSetAttribute(argmax_mma_kernel, cudaFuncAttributeMaxDynamicSharedMemorySize, SM_BYTES);

    zero_kernel<<<(K * D + 1023) / 1024, 1024>>>();
    enorm_kernel<<<K / 8, 256>>>(embed);
    argmax_mma_kernel<<<N_ROWS / BM, NT, SM_BYTES>>>(x, embed);
    cleanup_kernel<<<128, 256>>>(x, embed);
    scatter_kernel<<<N_ROWS / 8, 256>>>(x, embed, out, out_size);
    cs_kernel<<<(K + 255) / 256, 256>>>(cs, out, out_size);
    finalize_kernel<<<(K * D + 255) / 256, 256>>>(cs, ea, out, out_size);
}